// round 1
// baseline (speedup 1.0000x reference)
#include <cuda_runtime.h>

// CrossCCC: out = 1 - mean_n CCC(lag n), n = 0..249
//
// Decomposition:
//   Sg = sum g, Qg = sum g^2, Sp = sum p, Qp = sum p^2          (one pass)
//   C'(n) = sum_{j} p[j] * gpad[j+n]   (gpad zero-extended)     (the heavy part)
//   S_p(n) = Sp - tail_p(n), Q_p(n) = Qp - tail_q(n)            (last 250 elems of p)
//   cov(n) = (C'(n) - mean_gt * S_p(n)) / T
//   ccc(n) = 2 cov / (var_gt + var_pred + (mean_gt - mean_pred)^2)

#define NL        256      // padded lag count (250 used)
#define NLAGS     250
#define CHUNK     2048
#define MAXBLK    512
#define NTHREADS  256

__device__ float d_Cpart[MAXBLK][NL];
__device__ float d_sums[MAXBLK][4];   // Sp, Qp, Sg, Qg partials

__global__ void __launch_bounds__(NTHREADS)
cross_kernel(const float* __restrict__ p, const float* __restrict__ g,
             int T, int nchunks) {
    __shared__ float sp[CHUNK];
    __shared__ float sg[CHUNK + NL];
    __shared__ float red[NTHREADS / 32];

    const int tid  = threadIdx.x;
    const int n0   = (tid >> 3) * 8;   // 8 lags per thread
    const int jsub = tid & 7;          // 8 j-subthreads per lag group

    float acc[8];
#pragma unroll
    for (int i = 0; i < 8; i++) acc[i] = 0.f;
    float s_p = 0.f, q_p = 0.f, s_g = 0.f, q_g = 0.f;

    for (int c = blockIdx.x; c < nchunks; c += gridDim.x) {
        const long long j0 = (long long)c * CHUNK;
        // load p tile (+ running sums)
        for (int i = tid; i < CHUNK; i += NTHREADS) {
            long long gi = j0 + i;
            float v = (gi < T) ? p[gi] : 0.f;
            sp[i] = v;
            s_p += v; q_p += v * v;
        }
        // load g tile with NL-float halo, zero padded past T
        for (int i = tid; i < CHUNK + NL; i += NTHREADS) {
            long long gi = j0 + i;
            float v = (gi < T) ? g[gi] : 0.f;
            sg[i] = v;
            if (i < CHUNK) { s_g += v; q_g += v * v; }
        }
        __syncthreads();

        // 8 lags x 4 j register blocking: 4x LDS.128 per 32 FMAs
        for (int k = jsub * 4; k < CHUNK; k += 32) {
            float4 pv = *reinterpret_cast<const float4*>(sp + k);
            const float* gw = sg + k + n0;
            float4 g0 = *reinterpret_cast<const float4*>(gw);
            float4 g1 = *reinterpret_cast<const float4*>(gw + 4);
            float4 g2 = *reinterpret_cast<const float4*>(gw + 8);
            float gv[12] = {g0.x, g0.y, g0.z, g0.w,
                            g1.x, g1.y, g1.z, g1.w,
                            g2.x, g2.y, g2.z, g2.w};
            float pj[4] = {pv.x, pv.y, pv.z, pv.w};
#pragma unroll
            for (int dj = 0; dj < 4; dj++)
#pragma unroll
                for (int dn = 0; dn < 8; dn++)
                    acc[dn] = fmaf(pj[dj], gv[dj + dn], acc[dn]);
        }
        __syncthreads();
    }

    // reduce 8-lane j-subgroups (contiguous lanes) via shuffle
#pragma unroll
    for (int dn = 0; dn < 8; dn++) {
        float v = acc[dn];
        v += __shfl_down_sync(0xFFFFFFFFu, v, 4);
        v += __shfl_down_sync(0xFFFFFFFFu, v, 2);
        v += __shfl_down_sync(0xFFFFFFFFu, v, 1);
        acc[dn] = v;
    }
    if (jsub == 0) {
#pragma unroll
        for (int dn = 0; dn < 8; dn++)
            d_Cpart[blockIdx.x][n0 + dn] = acc[dn];
    }

    // block-reduce the 4 scalar sums
    float vals[4] = {s_p, q_p, s_g, q_g};
    for (int v = 0; v < 4; v++) {
        float x = vals[v];
#pragma unroll
        for (int off = 16; off > 0; off >>= 1)
            x += __shfl_down_sync(0xFFFFFFFFu, x, off);
        if ((tid & 31) == 0) red[tid >> 5] = x;
        __syncthreads();
        if (tid == 0) {
            float s = 0.f;
            for (int w = 0; w < NTHREADS / 32; w++) s += red[w];
            d_sums[blockIdx.x][v] = s;
        }
        __syncthreads();
    }
}

__global__ void __launch_bounds__(NTHREADS)
final_kernel(const float* __restrict__ p, float* __restrict__ out,
             int T, int nblk) {
    const int tid = threadIdx.x;
    __shared__ double sh_sums[4];
    __shared__ double sh_ccc[NL];

    if (tid < 4) {
        double s = 0.0;
        for (int b = 0; b < nblk; b++) s += (double)d_sums[b][tid];
        sh_sums[tid] = s;
    }

    // per-lag cross-correlation total
    double Cn = 0.0;
    if (tid < NL) {
        for (int b = 0; b < nblk; b++) Cn += (double)d_Cpart[b][tid];
    }

    // tail sums over last n elements of p
    double tp = 0.0, tq = 0.0;
    if (tid < NLAGS) {
        for (int i = 1; i <= tid; i++) {
            double v = (double)p[T - i];
            tp += v; tq += v * v;
        }
    }
    __syncthreads();

    double ccc = 0.0;
    if (tid < NLAGS) {
        const double Td = (double)T;
        double Sp = sh_sums[0] - tp, Qp = sh_sums[1] - tq;
        double Sg = sh_sums[2],      Qg = sh_sums[3];
        double mean_gt   = Sg / Td;
        double var_gt    = (Qg - Sg * Sg / Td) / (Td - 1.0);
        double mean_pred = Sp / Td;
        double var_pred  = (Qp - Sp * Sp / Td) / (Td - 1.0);
        double cov       = (Cn - mean_gt * Sp) / Td;
        double dm        = mean_gt - mean_pred;
        double denom     = var_gt + var_pred + dm * dm;
        ccc = 2.0 * cov / denom;
    }
    sh_ccc[tid] = ccc;
    __syncthreads();
    if (tid == 0) {
        double s = 0.0;
        for (int i = 0; i < NLAGS; i++) s += sh_ccc[i];
        out[0] = (float)(1.0 - s / (double)NLAGS);
    }
}

extern "C" void kernel_launch(void* const* d_in, const int* in_sizes, int n_in,
                              void* d_out, int out_size) {
    const float* p = (const float*)d_in[0];   // prediction
    const float* g = (const float*)d_in[1];   // ground_truth
    int T = in_sizes[0];
    int nchunks = (T + CHUNK - 1) / CHUNK;
    int grid = nchunks < MAXBLK ? nchunks : MAXBLK;
    cross_kernel<<<grid, NTHREADS>>>(p, g, T, nchunks);
    final_kernel<<<1, NTHREADS>>>(p, (float*)d_out, T, grid);
}

// round 2
// speedup vs baseline: 3.2822x; 3.2822x over previous
#include <cuda_runtime.h>

// CrossCCC: out = 1 - mean_n CCC(lag n), n = 0..249
//
// Decomposition:
//   Sg = sum g, Qg = sum g^2, Sp = sum p, Qp = sum p^2          (one pass)
//   C'(n) = sum_{j} p[j] * gpad[j+n]   (gpad zero-extended)     (the heavy part)
//   S_p(n) = Sp - tail_p(n), Q_p(n) = Qp - tail_q(n)            (last 250 elems of p)
//   cov(n) = (C'(n) - mean_gt * S_p(n)) / T
//   ccc(n) = 2 cov / (var_gt + var_pred + (mean_gt - mean_pred)^2)

#define NL        256      // padded lag count (250 used)
#define NLAGS     250
#define CHUNK     2048
#define MAXBLK    512
#define NTHREADS  256
#define RTHREADS  1024

__device__ float d_Cpart[MAXBLK][NL];
__device__ float d_sums[MAXBLK][4];   // Sp, Qp, Sg, Qg partials

__global__ void __launch_bounds__(NTHREADS)
cross_kernel(const float* __restrict__ p, const float* __restrict__ g,
             int T, int nchunks) {
    __shared__ float sp[CHUNK];
    __shared__ float sg[CHUNK + NL];
    __shared__ float red[NTHREADS / 32];

    const int tid  = threadIdx.x;
    const int n0   = (tid >> 3) * 8;   // 8 lags per thread
    const int jsub = tid & 7;          // 8 j-subthreads per lag group

    float acc[8];
#pragma unroll
    for (int i = 0; i < 8; i++) acc[i] = 0.f;
    float s_p = 0.f, q_p = 0.f, s_g = 0.f, q_g = 0.f;

    for (int c = blockIdx.x; c < nchunks; c += gridDim.x) {
        const long long j0 = (long long)c * CHUNK;
        // load p tile (+ running sums)
        for (int i = tid; i < CHUNK; i += NTHREADS) {
            long long gi = j0 + i;
            float v = (gi < T) ? p[gi] : 0.f;
            sp[i] = v;
            s_p += v; q_p += v * v;
        }
        // load g tile with NL-float halo, zero padded past T
        for (int i = tid; i < CHUNK + NL; i += NTHREADS) {
            long long gi = j0 + i;
            float v = (gi < T) ? g[gi] : 0.f;
            sg[i] = v;
            if (i < CHUNK) { s_g += v; q_g += v * v; }
        }
        __syncthreads();

        // 8 lags x 4 j register blocking: 4x LDS.128 per 32 FMAs
        for (int k = jsub * 4; k < CHUNK; k += 32) {
            float4 pv = *reinterpret_cast<const float4*>(sp + k);
            const float* gw = sg + k + n0;
            float4 g0 = *reinterpret_cast<const float4*>(gw);
            float4 g1 = *reinterpret_cast<const float4*>(gw + 4);
            float4 g2 = *reinterpret_cast<const float4*>(gw + 8);
            float gv[12] = {g0.x, g0.y, g0.z, g0.w,
                            g1.x, g1.y, g1.z, g1.w,
                            g2.x, g2.y, g2.z, g2.w};
            float pj[4] = {pv.x, pv.y, pv.z, pv.w};
#pragma unroll
            for (int dj = 0; dj < 4; dj++)
#pragma unroll
                for (int dn = 0; dn < 8; dn++)
                    acc[dn] = fmaf(pj[dj], gv[dj + dn], acc[dn]);
        }
        __syncthreads();
    }

    // reduce 8-lane j-subgroups (contiguous lanes) via shuffle
#pragma unroll
    for (int dn = 0; dn < 8; dn++) {
        float v = acc[dn];
        v += __shfl_down_sync(0xFFFFFFFFu, v, 4);
        v += __shfl_down_sync(0xFFFFFFFFu, v, 2);
        v += __shfl_down_sync(0xFFFFFFFFu, v, 1);
        acc[dn] = v;
    }
    if (jsub == 0) {
#pragma unroll
        for (int dn = 0; dn < 8; dn++)
            d_Cpart[blockIdx.x][n0 + dn] = acc[dn];
    }

    // block-reduce the 4 scalar sums
    float vals[4] = {s_p, q_p, s_g, q_g};
    for (int v = 0; v < 4; v++) {
        float x = vals[v];
#pragma unroll
        for (int off = 16; off > 0; off >>= 1)
            x += __shfl_down_sync(0xFFFFFFFFu, x, off);
        if ((tid & 31) == 0) red[tid >> 5] = x;
        __syncthreads();
        if (tid == 0) {
            float s = 0.f;
            for (int w = 0; w < NTHREADS / 32; w++) s += red[w];
            d_sums[blockIdx.x][v] = s;
        }
        __syncthreads();
    }
}

// Fully-parallel finalizer: 1 block x 1024 threads.
//   - C reduction: (part 0..3) x (lag 0..255), float accumulation, 2-way ILP
//   - scalar sums: 4 warps, shuffle-tree, double
//   - tail sums: Hillis-Steele prefix scan over the last 256 elements of p
//   - CCC formula in double + tree reduction of the 250 lag values
__global__ void __launch_bounds__(RTHREADS)
final_kernel(const float* __restrict__ p, float* __restrict__ out,
             int T, int nblk) {
    const int tid  = threadIdx.x;
    const int lag  = tid & (NL - 1);
    const int part = tid >> 8;          // 0..3

    __shared__ float  shC[4][NL];
    __shared__ double sh_sums[4];
    __shared__ double prefp[NL];
    __shared__ double prefq[NL];
    __shared__ double cccsh[NL];

    // ---- cross-block C reduction (parallel over 4 slices x 256 lags) ----
    float a0 = 0.f, a1 = 0.f;
    for (int b = part; b < nblk; b += 8)     a0 += d_Cpart[b][lag];
    for (int b = part + 4; b < nblk; b += 8) a1 += d_Cpart[b][lag];
    shC[part][lag] = a0 + a1;

    // ---- scalar sums (4 warps, one value each) ----
    if (tid < 128) {
        int v = tid >> 5, lane = tid & 31;
        double sv = 0.0;
        for (int b = lane; b < nblk; b += 32) sv += (double)d_sums[b][v];
#pragma unroll
        for (int off = 16; off > 0; off >>= 1)
            sv += __shfl_down_sync(0xFFFFFFFFu, sv, off);
        if (lane == 0) sh_sums[v] = sv;
    }

    // ---- tail prefix sums: tail_p(n) = sum_{i=1..n} p[T-i] ----
    if (tid < NL) {
        double w = (tid >= 1) ? (double)p[T - tid] : 0.0;
        prefp[tid] = w;
        prefq[tid] = w * w;
    }
    __syncthreads();
#pragma unroll
    for (int off = 1; off < NL; off <<= 1) {
        double a = 0.0, b = 0.0;
        if (tid < NL && tid >= off) { a = prefp[tid - off]; b = prefq[tid - off]; }
        __syncthreads();
        if (tid < NL) { prefp[tid] += a; prefq[tid] += b; }
        __syncthreads();
    }

    // ---- per-lag CCC ----
    double ccc = 0.0;
    if (tid < NLAGS) {
        double Cn = (double)shC[0][tid] + (double)shC[1][tid]
                  + (double)shC[2][tid] + (double)shC[3][tid];
        double tp = prefp[tid], tq = prefq[tid];   // pref[0] == 0

        const double Td = (double)T;
        double Sp = sh_sums[0] - tp, Qp = sh_sums[1] - tq;
        double Sg = sh_sums[2],      Qg = sh_sums[3];
        double mean_gt   = Sg / Td;
        double var_gt    = (Qg - Sg * Sg / Td) / (Td - 1.0);
        double mean_pred = Sp / Td;
        double var_pred  = (Qp - Sp * Sp / Td) / (Td - 1.0);
        double cov       = (Cn - mean_gt * Sp) / Td;
        double dm        = mean_gt - mean_pred;
        double denom     = var_gt + var_pred + dm * dm;
        ccc = 2.0 * cov / denom;
    }
    if (tid < NL) cccsh[tid] = ccc;   // lags 250..255 contribute 0
    __syncthreads();

    // ---- tree-reduce 256 lag values ----
#pragma unroll
    for (int off = NL / 2; off > 0; off >>= 1) {
        if (tid < off) cccsh[tid] += cccsh[tid + off];
        __syncthreads();
    }
    if (tid == 0) out[0] = (float)(1.0 - cccsh[0] / (double)NLAGS);
}

extern "C" void kernel_launch(void* const* d_in, const int* in_sizes, int n_in,
                              void* d_out, int out_size) {
    const float* p = (const float*)d_in[0];   // prediction
    const float* g = (const float*)d_in[1];   // ground_truth
    int T = in_sizes[0];
    int nchunks = (T + CHUNK - 1) / CHUNK;
    int grid = nchunks < MAXBLK ? nchunks : MAXBLK;
    cross_kernel<<<grid, NTHREADS>>>(p, g, T, nchunks);
    final_kernel<<<1, RTHREADS>>>(p, (float*)d_out, T, grid);
}

// round 3
// speedup vs baseline: 3.3163x; 1.0104x over previous
#include <cuda_runtime.h>

// CrossCCC: out = 1 - mean_n CCC(lag n), n = 0..249
//
// Decomposition:
//   Sg = sum g, Qg = sum g^2, Sp = sum p, Qp = sum p^2          (one pass)
//   C'(n) = sum_{j} p[j] * gpad[j+n]   (gpad zero-extended)     (the heavy part)
//   S_p(n) = Sp - tail_p(n), Q_p(n) = Qp - tail_q(n)            (last 250 elems of p)
//   cov(n) = (C'(n) - mean_gt * S_p(n)) / T
//   ccc(n) = 2 cov / (var_gt + var_pred + (mean_gt - mean_pred)^2)

#define NL        256      // padded lag count (250 used)
#define NLAGS     250
#define CHUNK     2048
#define MAXBLK    512
#define NTHREADS  256
#define RTHREADS  1024

__device__ float d_Cpart[MAXBLK][NL];
__device__ float d_sums[MAXBLK][4];   // Sp, Qp, Sg, Qg partials

__global__ void __launch_bounds__(NTHREADS)
cross_kernel(const float* __restrict__ p, const float* __restrict__ g,
             int T, int nchunks) {
    __shared__ float sp[CHUNK];
    __shared__ float sg[CHUNK + NL];
    __shared__ float red[NTHREADS / 32];

    const int tid  = threadIdx.x;
    const int n0   = (tid >> 3) * 8;   // 8 lags per thread
    const int jsub = tid & 7;          // 8 j-subthreads per lag group

    float acc[8];
#pragma unroll
    for (int i = 0; i < 8; i++) acc[i] = 0.f;
    float s_p = 0.f, q_p = 0.f, s_g = 0.f, q_g = 0.f;

    for (int c = blockIdx.x; c < nchunks; c += gridDim.x) {
        const long long j0 = (long long)c * CHUNK;
        // load p tile (+ running sums)
        for (int i = tid; i < CHUNK; i += NTHREADS) {
            long long gi = j0 + i;
            float v = (gi < T) ? p[gi] : 0.f;
            sp[i] = v;
            s_p += v; q_p += v * v;
        }
        // load g tile with NL-float halo, zero padded past T
        for (int i = tid; i < CHUNK + NL; i += NTHREADS) {
            long long gi = j0 + i;
            float v = (gi < T) ? g[gi] : 0.f;
            sg[i] = v;
            if (i < CHUNK) { s_g += v; q_g += v * v; }
        }
        __syncthreads();

        // 8 lags x 4 j register blocking: 4x LDS.128 per 32 FMAs
        for (int k = jsub * 4; k < CHUNK; k += 32) {
            float4 pv = *reinterpret_cast<const float4*>(sp + k);
            const float* gw = sg + k + n0;
            float4 g0 = *reinterpret_cast<const float4*>(gw);
            float4 g1 = *reinterpret_cast<const float4*>(gw + 4);
            float4 g2 = *reinterpret_cast<const float4*>(gw + 8);
            float gv[12] = {g0.x, g0.y, g0.z, g0.w,
                            g1.x, g1.y, g1.z, g1.w,
                            g2.x, g2.y, g2.z, g2.w};
            float pj[4] = {pv.x, pv.y, pv.z, pv.w};
#pragma unroll
            for (int dj = 0; dj < 4; dj++)
#pragma unroll
                for (int dn = 0; dn < 8; dn++)
                    acc[dn] = fmaf(pj[dj], gv[dj + dn], acc[dn]);
        }
        __syncthreads();
    }

    // reduce 8-lane j-subgroups (contiguous lanes) via shuffle
#pragma unroll
    for (int dn = 0; dn < 8; dn++) {
        float v = acc[dn];
        v += __shfl_down_sync(0xFFFFFFFFu, v, 4);
        v += __shfl_down_sync(0xFFFFFFFFu, v, 2);
        v += __shfl_down_sync(0xFFFFFFFFu, v, 1);
        acc[dn] = v;
    }
    if (jsub == 0) {
#pragma unroll
        for (int dn = 0; dn < 8; dn++)
            d_Cpart[blockIdx.x][n0 + dn] = acc[dn];
    }

    // block-reduce the 4 scalar sums
    float vals[4] = {s_p, q_p, s_g, q_g};
    for (int v = 0; v < 4; v++) {
        float x = vals[v];
#pragma unroll
        for (int off = 16; off > 0; off >>= 1)
            x += __shfl_down_sync(0xFFFFFFFFu, x, off);
        if ((tid & 31) == 0) red[tid >> 5] = x;
        __syncthreads();
        if (tid == 0) {
            float s = 0.f;
            for (int w = 0; w < NTHREADS / 32; w++) s += red[w];
            d_sums[blockIdx.x][v] = s;
        }
        __syncthreads();
    }
}

// Fully-parallel finalizer: 1 block x 1024 threads.
//   - C reduction: (part 0..3) x (lag 0..255), float accumulation, 2-way ILP
//   - scalar sums: 4 warps, shuffle-tree, double
//   - tail sums: Hillis-Steele prefix scan over the last 256 elements of p
//   - CCC formula in double + tree reduction of the 250 lag values
__global__ void __launch_bounds__(RTHREADS)
final_kernel(const float* __restrict__ p, float* __restrict__ out,
             int T, int nblk) {
    const int tid  = threadIdx.x;
    const int lag  = tid & (NL - 1);
    const int part = tid >> 8;          // 0..3

    __shared__ float  shC[4][NL];
    __shared__ double sh_sums[4];
    __shared__ double prefp[NL];
    __shared__ double prefq[NL];
    __shared__ double cccsh[NL];

    // ---- cross-block C reduction (parallel over 4 slices x 256 lags) ----
    float a0 = 0.f, a1 = 0.f;
    for (int b = part; b < nblk; b += 8)     a0 += d_Cpart[b][lag];
    for (int b = part + 4; b < nblk; b += 8) a1 += d_Cpart[b][lag];
    shC[part][lag] = a0 + a1;

    // ---- scalar sums (4 warps, one value each) ----
    if (tid < 128) {
        int v = tid >> 5, lane = tid & 31;
        double sv = 0.0;
        for (int b = lane; b < nblk; b += 32) sv += (double)d_sums[b][v];
#pragma unroll
        for (int off = 16; off > 0; off >>= 1)
            sv += __shfl_down_sync(0xFFFFFFFFu, sv, off);
        if (lane == 0) sh_sums[v] = sv;
    }

    // ---- tail prefix sums: tail_p(n) = sum_{i=1..n} p[T-i] ----
    if (tid < NL) {
        double w = (tid >= 1) ? (double)p[T - tid] : 0.0;
        prefp[tid] = w;
        prefq[tid] = w * w;
    }
    __syncthreads();
#pragma unroll
    for (int off = 1; off < NL; off <<= 1) {
        double a = 0.0, b = 0.0;
        if (tid < NL && tid >= off) { a = prefp[tid - off]; b = prefq[tid - off]; }
        __syncthreads();
        if (tid < NL) { prefp[tid] += a; prefq[tid] += b; }
        __syncthreads();
    }

    // ---- per-lag CCC ----
    double ccc = 0.0;
    if (tid < NLAGS) {
        double Cn = (double)shC[0][tid] + (double)shC[1][tid]
                  + (double)shC[2][tid] + (double)shC[3][tid];
        double tp = prefp[tid], tq = prefq[tid];   // pref[0] == 0

        const double Td = (double)T;
        double Sp = sh_sums[0] - tp, Qp = sh_sums[1] - tq;
        double Sg = sh_sums[2],      Qg = sh_sums[3];
        double mean_gt   = Sg / Td;
        double var_gt    = (Qg - Sg * Sg / Td) / (Td - 1.0);
        double mean_pred = Sp / Td;
        double var_pred  = (Qp - Sp * Sp / Td) / (Td - 1.0);
        double cov       = (Cn - mean_gt * Sp) / Td;
        double dm        = mean_gt - mean_pred;
        double denom     = var_gt + var_pred + dm * dm;
        ccc = 2.0 * cov / denom;
    }
    if (tid < NL) cccsh[tid] = ccc;   // lags 250..255 contribute 0
    __syncthreads();

    // ---- tree-reduce 256 lag values ----
#pragma unroll
    for (int off = NL / 2; off > 0; off >>= 1) {
        if (tid < off) cccsh[tid] += cccsh[tid + off];
        __syncthreads();
    }
    if (tid == 0) out[0] = (float)(1.0 - cccsh[0] / (double)NLAGS);
}

extern "C" void kernel_launch(void* const* d_in, const int* in_sizes, int n_in,
                              void* d_out, int out_size) {
    const float* p = (const float*)d_in[0];   // prediction
    const float* g = (const float*)d_in[1];   // ground_truth
    int T = in_sizes[0];
    int nchunks = (T + CHUNK - 1) / CHUNK;
    int grid = nchunks < MAXBLK ? nchunks : MAXBLK;
    cross_kernel<<<grid, NTHREADS>>>(p, g, T, nchunks);
    final_kernel<<<1, RTHREADS>>>(p, (float*)d_out, T, grid);
}

// round 4
// speedup vs baseline: 3.7653x; 1.1354x over previous
#include <cuda_runtime.h>

// CrossCCC: out = 1 - mean_n CCC(lag n), n = 0..249
//
// Decomposition:
//   Sg = sum g, Qg = sum g^2, Sp = sum p, Qp = sum p^2          (one pass)
//   C'(n) = sum_{j} p[j] * gpad[j+n]   (gpad zero-extended)     (the heavy part)
//   S_p(n) = Sp - tail_p(n), Q_p(n) = Qp - tail_q(n)            (last 250 elems of p)
//   cov(n) = (C'(n) - mean_gt * S_p(n)) / T
//   ccc(n) = 2 cov / (var_gt + var_pred + (mean_gt - mean_pred)^2)

#define NL        256      // padded lag count (250 used)
#define NLAGS     250
#define CHUNK     2048
#define MAXBLK    512
#define GRIDCAP   296      // 2 CTAs per SM on 148-SM GB300
#define NTHREADS  256
#define RTHREADS  1024

__device__ float d_Cpart[MAXBLK][NL];
__device__ float d_sums[MAXBLK][4];   // Sp, Qp, Sg, Qg partials

__global__ void __launch_bounds__(NTHREADS)
cross_kernel(const float* __restrict__ p, const float* __restrict__ g,
             int T, int nchunks) {
    __shared__ float sp[CHUNK];
    __shared__ float sg[CHUNK + NL];
    __shared__ float red[NTHREADS / 32];

    const int tid  = threadIdx.x;
    const int n0   = (tid >> 3) * 8;   // 8 lags per thread
    const int jsub = tid & 7;          // 8 j-subthreads per lag group

    float acc[8];
#pragma unroll
    for (int i = 0; i < 8; i++) acc[i] = 0.f;
    float s_p = 0.f, q_p = 0.f, s_g = 0.f, q_g = 0.f;

    for (int c = blockIdx.x; c < nchunks; c += gridDim.x) {
        const long long j0 = (long long)c * CHUNK;
        // load p tile (+ running sums)
        for (int i = tid; i < CHUNK; i += NTHREADS) {
            long long gi = j0 + i;
            float v = (gi < T) ? p[gi] : 0.f;
            sp[i] = v;
            s_p += v; q_p += v * v;
        }
        // load g tile with NL-float halo, zero padded past T
        for (int i = tid; i < CHUNK + NL; i += NTHREADS) {
            long long gi = j0 + i;
            float v = (gi < T) ? g[gi] : 0.f;
            sg[i] = v;
            if (i < CHUNK) { s_g += v; q_g += v * v; }
        }
        __syncthreads();

        // 8 lags x 4 j register blocking: 4x LDS.128 per 32 FMAs
        for (int k = jsub * 4; k < CHUNK; k += 32) {
            float4 pv = *reinterpret_cast<const float4*>(sp + k);
            const float* gw = sg + k + n0;
            float4 g0 = *reinterpret_cast<const float4*>(gw);
            float4 g1 = *reinterpret_cast<const float4*>(gw + 4);
            float4 g2 = *reinterpret_cast<const float4*>(gw + 8);
            float gv[12] = {g0.x, g0.y, g0.z, g0.w,
                            g1.x, g1.y, g1.z, g1.w,
                            g2.x, g2.y, g2.z, g2.w};
            float pj[4] = {pv.x, pv.y, pv.z, pv.w};
#pragma unroll
            for (int dj = 0; dj < 4; dj++)
#pragma unroll
                for (int dn = 0; dn < 8; dn++)
                    acc[dn] = fmaf(pj[dj], gv[dj + dn], acc[dn]);
        }
        __syncthreads();
    }

    // reduce 8-lane j-subgroups (contiguous lanes) via shuffle
#pragma unroll
    for (int dn = 0; dn < 8; dn++) {
        float v = acc[dn];
        v += __shfl_down_sync(0xFFFFFFFFu, v, 4);
        v += __shfl_down_sync(0xFFFFFFFFu, v, 2);
        v += __shfl_down_sync(0xFFFFFFFFu, v, 1);
        acc[dn] = v;
    }
    if (jsub == 0) {
#pragma unroll
        for (int dn = 0; dn < 8; dn++)
            d_Cpart[blockIdx.x][n0 + dn] = acc[dn];
    }

    // block-reduce the 4 scalar sums
    float vals[4] = {s_p, q_p, s_g, q_g};
    for (int v = 0; v < 4; v++) {
        float x = vals[v];
#pragma unroll
        for (int off = 16; off > 0; off >>= 1)
            x += __shfl_down_sync(0xFFFFFFFFu, x, off);
        if ((tid & 31) == 0) red[tid >> 5] = x;
        __syncthreads();
        if (tid == 0) {
            float s = 0.f;
            for (int w = 0; w < NTHREADS / 32; w++) s += red[w];
            d_sums[blockIdx.x][v] = s;
        }
        __syncthreads();
    }
}

// Fully-parallel finalizer: 1 block x 1024 threads.
//   - C reduction: (part 0..3) x (lag 0..255), float accumulation, MLP=4
//   - scalar sums: 4 warps, shuffle-tree, double
//   - tail sums: Hillis-Steele prefix scan over the last 256 elements of p
//   - CCC formula in double + tree reduction of the 250 lag values
__global__ void __launch_bounds__(RTHREADS)
final_kernel(const float* __restrict__ p, float* __restrict__ out,
             int T, int nblk) {
    const int tid  = threadIdx.x;
    const int lag  = tid & (NL - 1);
    const int part = tid >> 8;          // 0..3

    __shared__ float  shC[4][NL];
    __shared__ double sh_sums[4];
    __shared__ double prefp[NL];
    __shared__ double prefq[NL];
    __shared__ double cccsh[NL];

    // ---- cross-block C reduction: 4 independent accumulators -> MLP 4 ----
    {
        float a0 = 0.f, a1 = 0.f, a2 = 0.f, a3 = 0.f;
        int b = part;
        for (; b + 12 < nblk; b += 16) {
            a0 += d_Cpart[b     ][lag];
            a1 += d_Cpart[b +  4][lag];
            a2 += d_Cpart[b +  8][lag];
            a3 += d_Cpart[b + 12][lag];
        }
        for (; b < nblk; b += 4) a0 += d_Cpart[b][lag];
        shC[part][lag] = (a0 + a1) + (a2 + a3);
    }

    // ---- scalar sums (4 warps, one value each, MLP via strided lanes) ----
    if (tid < 128) {
        int v = tid >> 5, lane = tid & 31;
        double sv = 0.0;
        for (int b = lane; b < nblk; b += 32) sv += (double)d_sums[b][v];
#pragma unroll
        for (int off = 16; off > 0; off >>= 1)
            sv += __shfl_down_sync(0xFFFFFFFFu, sv, off);
        if (lane == 0) sh_sums[v] = sv;
    }

    // ---- tail prefix sums: tail_p(n) = sum_{i=1..n} p[T-i] ----
    if (tid < NL) {
        double w = (tid >= 1) ? (double)p[T - tid] : 0.0;
        prefp[tid] = w;
        prefq[tid] = w * w;
    }
    __syncthreads();
#pragma unroll
    for (int off = 1; off < NL; off <<= 1) {
        double a = 0.0, b = 0.0;
        if (tid < NL && tid >= off) { a = prefp[tid - off]; b = prefq[tid - off]; }
        __syncthreads();
        if (tid < NL) { prefp[tid] += a; prefq[tid] += b; }
        __syncthreads();
    }

    // ---- per-lag CCC ----
    double ccc = 0.0;
    if (tid < NLAGS) {
        double Cn = (double)shC[0][tid] + (double)shC[1][tid]
                  + (double)shC[2][tid] + (double)shC[3][tid];
        double tp = prefp[tid], tq = prefq[tid];   // pref[0] == 0

        const double Td   = (double)T;
        const double rT   = 1.0 / Td;
        const double rT1  = 1.0 / (Td - 1.0);
        double Sp = sh_sums[0] - tp, Qp = sh_sums[1] - tq;
        double Sg = sh_sums[2],      Qg = sh_sums[3];
        double mean_gt   = Sg * rT;
        double var_gt    = (Qg - Sg * Sg * rT) * rT1;
        double mean_pred = Sp * rT;
        double var_pred  = (Qp - Sp * Sp * rT) * rT1;
        double cov       = (Cn - mean_gt * Sp) * rT;
        double dm        = mean_gt - mean_pred;
        double denom     = var_gt + var_pred + dm * dm;
        ccc = 2.0 * cov / denom;
    }
    if (tid < NL) cccsh[tid] = ccc;   // lags 250..255 contribute 0
    __syncthreads();

    // ---- tree-reduce 256 lag values ----
#pragma unroll
    for (int off = NL / 2; off > 0; off >>= 1) {
        if (tid < off) cccsh[tid] += cccsh[tid + off];
        __syncthreads();
    }
    if (tid == 0) out[0] = (float)(1.0 - cccsh[0] / (double)NLAGS);
}

extern "C" void kernel_launch(void* const* d_in, const int* in_sizes, int n_in,
                              void* d_out, int out_size) {
    const float* p = (const float*)d_in[0];   // prediction
    const float* g = (const float*)d_in[1];   // ground_truth
    int T = in_sizes[0];
    int nchunks = (T + CHUNK - 1) / CHUNK;
    int grid = nchunks < GRIDCAP ? nchunks : GRIDCAP;
    cross_kernel<<<grid, NTHREADS>>>(p, g, T, nchunks);
    final_kernel<<<1, RTHREADS>>>(p, (float*)d_out, T, grid);
}

// round 5
// speedup vs baseline: 3.9483x; 1.0486x over previous
#include <cuda_runtime.h>

// CrossCCC: out = 1 - mean_n CCC(lag n), n = 0..249
// Single fused kernel: grid-stride tiled cross-correlation + per-block
// partials; the LAST block to finish (atomic ticket) reduces all partials
// and computes the final scalar. Deterministic: the finalize reads every
// block's partials in a fixed order regardless of which block runs it.

#define NL        256      // padded lag count (250 used)
#define NLAGS     250
#define CHUNK     2048
#define GRIDCAP   296      // 2 CTAs per SM on 148-SM GB300
#define NTHREADS  256

__device__ float d_Cpart[GRIDCAP][NL];
__device__ float d_sums[GRIDCAP][4];   // Sp, Qp, Sg, Qg partials
__device__ unsigned int d_ticket;      // zero-init; last block resets to 0

__global__ void __launch_bounds__(NTHREADS)
fused_kernel(const float* __restrict__ p, const float* __restrict__ g,
             float* __restrict__ out, int T, int nchunks) {
    __shared__ float sp[CHUNK];
    __shared__ float sg[CHUNK + NL];
    __shared__ float red[NTHREADS / 32];
    __shared__ int   s_last;

    const int tid  = threadIdx.x;
    const int n0   = (tid >> 3) * 8;   // 8 lags per thread
    const int jsub = tid & 7;          // 8 j-subthreads per lag group

    float acc[8];
#pragma unroll
    for (int i = 0; i < 8; i++) acc[i] = 0.f;
    float s_p = 0.f, q_p = 0.f, s_g = 0.f, q_g = 0.f;

    for (int c = blockIdx.x; c < nchunks; c += gridDim.x) {
        const long long j0 = (long long)c * CHUNK;
        for (int i = tid; i < CHUNK; i += NTHREADS) {
            long long gi = j0 + i;
            float v = (gi < T) ? p[gi] : 0.f;
            sp[i] = v;
            s_p += v; q_p += v * v;
        }
        for (int i = tid; i < CHUNK + NL; i += NTHREADS) {
            long long gi = j0 + i;
            float v = (gi < T) ? g[gi] : 0.f;
            sg[i] = v;
            if (i < CHUNK) { s_g += v; q_g += v * v; }
        }
        __syncthreads();

        // 8 lags x 4 j register blocking: 4x LDS.128 per 32 FMAs
        const float* gbase = sg + n0;
#pragma unroll 2
        for (int k = jsub * 4; k < CHUNK; k += 32) {
            float4 pv = *reinterpret_cast<const float4*>(sp + k);
            const float* gw = gbase + k;
            float4 g0 = *reinterpret_cast<const float4*>(gw);
            float4 g1 = *reinterpret_cast<const float4*>(gw + 4);
            float4 g2 = *reinterpret_cast<const float4*>(gw + 8);
            float gv[12] = {g0.x, g0.y, g0.z, g0.w,
                            g1.x, g1.y, g1.z, g1.w,
                            g2.x, g2.y, g2.z, g2.w};
            float pj[4] = {pv.x, pv.y, pv.z, pv.w};
#pragma unroll
            for (int dj = 0; dj < 4; dj++)
#pragma unroll
                for (int dn = 0; dn < 8; dn++)
                    acc[dn] = fmaf(pj[dj], gv[dj + dn], acc[dn]);
        }
        __syncthreads();
    }

    // reduce 8-lane j-subgroups (contiguous lanes) via shuffle
#pragma unroll
    for (int dn = 0; dn < 8; dn++) {
        float v = acc[dn];
        v += __shfl_down_sync(0xFFFFFFFFu, v, 4);
        v += __shfl_down_sync(0xFFFFFFFFu, v, 2);
        v += __shfl_down_sync(0xFFFFFFFFu, v, 1);
        acc[dn] = v;
    }
    if (jsub == 0) {
#pragma unroll
        for (int dn = 0; dn < 8; dn++)
            d_Cpart[blockIdx.x][n0 + dn] = acc[dn];
    }

    // block-reduce the 4 scalar sums
    float vals[4] = {s_p, q_p, s_g, q_g};
    for (int v = 0; v < 4; v++) {
        float x = vals[v];
#pragma unroll
        for (int off = 16; off > 0; off >>= 1)
            x += __shfl_down_sync(0xFFFFFFFFu, x, off);
        if ((tid & 31) == 0) red[tid >> 5] = x;
        __syncthreads();
        if (tid == 0) {
            float s = 0.f;
            for (int w = 0; w < NTHREADS / 32; w++) s += red[w];
            d_sums[blockIdx.x][v] = s;
        }
        __syncthreads();
    }

    // ---- last-block election ----
    __threadfence();   // make this block's partials globally visible
    if (tid == 0) {
        unsigned int old = atomicAdd(&d_ticket, 1u);
        s_last = (old == gridDim.x - 1) ? 1 : 0;
    }
    __syncthreads();
    if (!s_last) return;

    // =====================================================================
    // Finalize (runs in the last block; partials are L2-hot)
    // =====================================================================
    const int nblk = gridDim.x;
    __shared__ double sh_sums[4];
    __shared__ double prefp[NL];
    __shared__ double prefq[NL];
    __shared__ double cccsh[NL];

    // ---- cross-block C reduction: one lag per thread, 4 accumulators ----
    double Cn;
    {
        const int lag = tid;
        float a0 = 0.f, a1 = 0.f, a2 = 0.f, a3 = 0.f;
        int b = 0;
        for (; b + 3 < nblk; b += 4) {
            a0 += d_Cpart[b    ][lag];
            a1 += d_Cpart[b + 1][lag];
            a2 += d_Cpart[b + 2][lag];
            a3 += d_Cpart[b + 3][lag];
        }
        for (; b < nblk; b++) a0 += d_Cpart[b][lag];
        Cn = (double)((a0 + a1) + (a2 + a3));
    }

    // ---- scalar sums (4 warps, one value each) ----
    if (tid < 128) {
        int v = tid >> 5, lane = tid & 31;
        double sv = 0.0;
        for (int b = lane; b < nblk; b += 32) sv += (double)d_sums[b][v];
#pragma unroll
        for (int off = 16; off > 0; off >>= 1)
            sv += __shfl_down_sync(0xFFFFFFFFu, sv, off);
        if (lane == 0) sh_sums[v] = sv;
    }

    // ---- tail prefix sums: tail_p(n) = sum_{i=1..n} p[T-i] ----
    {
        double w = (tid >= 1) ? (double)p[T - tid] : 0.0;
        prefp[tid] = w;
        prefq[tid] = w * w;
    }
    __syncthreads();
#pragma unroll
    for (int off = 1; off < NL; off <<= 1) {
        double a = 0.0, b = 0.0;
        if (tid >= off) { a = prefp[tid - off]; b = prefq[tid - off]; }
        __syncthreads();
        prefp[tid] += a; prefq[tid] += b;
        __syncthreads();
    }

    // ---- per-lag CCC ----
    double ccc = 0.0;
    if (tid < NLAGS) {
        double tp = prefp[tid], tq = prefq[tid];   // pref[0] == 0
        const double Td  = (double)T;
        const double rT  = 1.0 / Td;
        const double rT1 = 1.0 / (Td - 1.0);
        double Sp = sh_sums[0] - tp, Qp = sh_sums[1] - tq;
        double Sg = sh_sums[2],      Qg = sh_sums[3];
        double mean_gt   = Sg * rT;
        double var_gt    = (Qg - Sg * Sg * rT) * rT1;
        double mean_pred = Sp * rT;
        double var_pred  = (Qp - Sp * Sp * rT) * rT1;
        double cov       = (Cn - mean_gt * Sp) * rT;
        double dm        = mean_gt - mean_pred;
        double denom     = var_gt + var_pred + dm * dm;
        ccc = 2.0 * cov / denom;
    }
    cccsh[tid] = ccc;   // lags 250..255 contribute 0
    __syncthreads();

#pragma unroll
    for (int off = NL / 2; off > 0; off >>= 1) {
        if (tid < off) cccsh[tid] += cccsh[tid + off];
        __syncthreads();
    }
    if (tid == 0) {
        out[0] = (float)(1.0 - cccsh[0] / (double)NLAGS);
        d_ticket = 0;   // restore for next graph replay
    }
}

extern "C" void kernel_launch(void* const* d_in, const int* in_sizes, int n_in,
                              void* d_out, int out_size) {
    const float* p = (const float*)d_in[0];   // prediction
    const float* g = (const float*)d_in[1];   // ground_truth
    int T = in_sizes[0];
    int nchunks = (T + CHUNK - 1) / CHUNK;
    int grid = nchunks < GRIDCAP ? nchunks : GRIDCAP;
    fused_kernel<<<grid, NTHREADS>>>(p, g, (float*)d_out, T, nchunks);
}